// round 15
// baseline (speedup 1.0000x reference)
#include <cuda_runtime.h>
#include <cstdint>
#include <cstddef>

// f = H @ x + damp * x per molecule.
// hess: [M*96, 96] f32 row-major, ns: flat [M*96] f32, out: flat [M*96] f32.
// FINAL converged config: 456 persistent CTAs (3/SM), 2-stage TMA ring, one
// mbarrier per stage, two bulk copies per molecule, L2 evict_first, LDS.128
// rotated consumer. 48.35us best kernel time vs 48.1us compulsory-traffic
// floor at the measured ~6.4TB/s LTS ceiling (99.5% of achievable).
#define D 96
#define D4 24                  // D/4 vec4 columns
#define DD (D * D)
#define H_BYTES (DD * 4)       // 36864
#define X_BYTES (D * 4)        // 384
#define NBLOCKS 456            // 152 SMs * 3 CTAs/SM (GB300)

// dynamic smem layout:
//   [0,            2*H_BYTES)              : H stages (2 x 36864)
//   [2*H_BYTES,    2*H_BYTES + 2*X_BYTES)  : x stages (2 x 384)
//   [...,          +16)                    : 2 mbarriers (8B each)
#define SMEM_X_OFF    (2 * H_BYTES)
#define SMEM_MBAR_OFF (2 * H_BYTES + 2 * X_BYTES)
#define SMEM_TOTAL    (SMEM_MBAR_OFF + 16)

__device__ __constant__ float kDampF = (float)(0.1 * 627.5094740631 /
                                               (0.529177210903 * 0.529177210903));

__device__ __forceinline__ uint32_t s2u(const void* p) {
    uint32_t a;
    asm("{ .reg .u64 t; cvta.to.shared.u64 t, %1; cvt.u32.u64 %0, t; }"
        : "=r"(a) : "l"(p));
    return a;
}

__device__ __forceinline__ void mbar_init(uint32_t mbar, uint32_t count) {
    asm volatile("mbarrier.init.shared.b64 [%0], %1;" :: "r"(mbar), "r"(count) : "memory");
}

__device__ __forceinline__ void mbar_expect_tx(uint32_t mbar, uint32_t bytes) {
    asm volatile("mbarrier.arrive.expect_tx.shared.b64 _, [%0], %1;"
                 :: "r"(mbar), "r"(bytes) : "memory");
}

__device__ __forceinline__ void mbar_wait(uint32_t mbar, uint32_t parity) {
    asm volatile(
        "{\n\t"
        ".reg .pred P;\n\t"
        "WAIT_%=:\n\t"
        "mbarrier.try_wait.parity.shared.b64 P, [%0], %1;\n\t"
        "@!P bra WAIT_%=;\n\t"
        "}"
        :: "r"(mbar), "r"(parity) : "memory");
}

// bulk G->S copy with L2 evict-first policy (zero-reuse 302MB stream)
__device__ __forceinline__ void bulk_g2s_ef(uint32_t dst_smem, const void* src_gmem,
                                            uint32_t bytes, uint32_t mbar) {
    asm volatile(
        "{\n\t"
        ".reg .b64 pol;\n\t"
        "createpolicy.fractional.L2::evict_first.b64 pol, 1.0;\n\t"
        "cp.async.bulk.shared::cluster.global.mbarrier::complete_tx::bytes.L2::cache_hint "
        "[%0], [%1], %2, [%3], pol;\n\t"
        "}"
        :: "r"(dst_smem), "l"(src_gmem), "r"(bytes), "r"(mbar) : "memory");
}

extern __shared__ char smem_raw[];

__global__ void __launch_bounds__(D, 3)
force_agg_kernel(const float* __restrict__ ns,
                 const float* __restrict__ hess,
                 float* __restrict__ out, int M) {
    float* Hs = reinterpret_cast<float*>(smem_raw);                 // [2][DD]
    float* xs = reinterpret_cast<float*>(smem_raw + SMEM_X_OFF);    // [2][D]
    const uint32_t mbar0 = s2u(smem_raw + SMEM_MBAR_OFF);
    const uint32_t mbar1 = mbar0 + 8;

    const int t = threadIdx.x;     // 0..95
    const int b = blockIdx.x;

    if (t == 0) {
        mbar_init(mbar0, 1);
        mbar_init(mbar1, 1);
    }
    __syncthreads();

    const int stride = gridDim.x;
    const int cnt = (M - b + stride - 1) / stride;

    const uint32_t Hs_u = s2u(Hs);
    const uint32_t xs_u = s2u(xs);

    // prologue: stage 0 for k=0
    if (t == 0) {
        mbar_expect_tx(mbar0, H_BYTES + X_BYTES);
        bulk_g2s_ef(Hs_u, hess + (size_t)b * DD, H_BYTES, mbar0);
        bulk_g2s_ef(xs_u, ns + (size_t)b * D, X_BYTES, mbar0);
    }

    uint32_t phase0 = 0, phase1 = 0;
    const int c0 = t % D4;         // rotated vec4-column start (conflict-free)

    const size_t mstepH = (size_t)stride * DD;
    const size_t mstepX = (size_t)stride * D;
    const float* hess_next = hess + (size_t)b * DD + mstepH;   // molecule k=1
    const float* ns_next   = ns   + (size_t)b * D  + mstepX;
    float* out_p           = out  + (size_t)b * D  + t;

    for (int k = 0; k < cnt; ++k) {
        const int s = k & 1;

        // prefetch k+1 into stage s^1 (freed by the sync ending iter k-1)
        if (t == 0 && (k + 1) < cnt) {
            const int s2 = s ^ 1;
            const uint32_t mbar_n = s2 ? mbar1 : mbar0;
            mbar_expect_tx(mbar_n, H_BYTES + X_BYTES);
            bulk_g2s_ef(Hs_u + (uint32_t)s2 * H_BYTES, hess_next, H_BYTES, mbar_n);
            bulk_g2s_ef(xs_u + (uint32_t)s2 * X_BYTES, ns_next, X_BYTES, mbar_n);
        }
        hess_next += mstepH;
        ns_next   += mstepX;

        // wait for stage s
        if (s) { mbar_wait(mbar1, phase1); phase1 ^= 1; }
        else   { mbar_wait(mbar0, phase0); phase0 ^= 1; }

        // vectorized dot product: LDS.128 on H row and x, rotated start.
        // 16B-group = (c mod 8): distinct within each 8-lane phase -> bank-free.
        const float4* __restrict__ Hrow4 =
            reinterpret_cast<const float4*>(Hs + (size_t)s * DD + (size_t)t * D);
        const float4* __restrict__ xv4 =
            reinterpret_cast<const float4*>(xs + s * D);

        float a0 = 0.f, a1 = 0.f, a2 = 0.f, a3 = 0.f;
        int c = c0;
        #pragma unroll
        for (int it = 0; it < D4; ++it) {
            float4 h = Hrow4[c];
            float4 xv = xv4[c];
            a0 = fmaf(h.x, xv.x, a0);
            a1 = fmaf(h.y, xv.y, a1);
            a2 = fmaf(h.z, xv.z, a2);
            a3 = fmaf(h.w, xv.w, a3);
            ++c;
            if (c == D4) c = 0;
        }
        const float x_t = (xs + s * D)[t];
        const float acc = fmaf(kDampF, x_t, (a0 + a1) + (a2 + a3));

        *out_p = acc;
        out_p += mstepX;

        // stage s must be fully consumed before iter k+1 refills it;
        // elide on the final iteration (nothing is refilled afterward)
        if ((k + 1) < cnt) __syncthreads();
    }
}

extern "C" void kernel_launch(void* const* d_in, const int* in_sizes, int n_in,
                              void* d_out, int out_size) {
    const float* ns   = (const float*)d_in[0];   // [N_tot,3] -> flat [M*96]
    const float* hess = (const float*)d_in[1];   // [M*96, 96]
    float* out = (float*)d_out;

    const int M = in_sizes[1] / DD;              // 8192

    cudaFuncSetAttribute(force_agg_kernel,
                         cudaFuncAttributeMaxDynamicSharedMemorySize, SMEM_TOTAL);
    force_agg_kernel<<<NBLOCKS, D, SMEM_TOTAL>>>(ns, hess, out, M);
}

// round 16
// speedup vs baseline: 1.0284x; 1.0284x over previous
#include <cuda_runtime.h>
#include <cstdint>
#include <cstddef>

// f = H @ x + damp * x per molecule.
// hess: [M*96, 96] f32 row-major, ns: flat [M*96] f32, out: flat [M*96] f32.
// FINAL converged config (best measured kernel time 47.74us, HBM 6.49TB/s =
// 81% of spec, ~99% of demonstrated chip ceiling for this stream):
// 456 persistent CTAs (3/SM), 2-stage TMA ring, one mbarrier per stage, two
// bulk copies per molecule, L2 evict_first, LDS.128 rotated-column consumer,
// final-iteration sync elision.
#define D 96
#define D4 24                  // D/4 vec4 columns
#define DD (D * D)
#define H_BYTES (DD * 4)       // 36864
#define X_BYTES (D * 4)        // 384
#define NBLOCKS 456            // 152 SMs * 3 CTAs/SM (GB300)

// dynamic smem layout:
//   [0,            2*H_BYTES)              : H stages (2 x 36864)
//   [2*H_BYTES,    2*H_BYTES + 2*X_BYTES)  : x stages (2 x 384)
//   [...,          +16)                    : 2 mbarriers (8B each)
#define SMEM_X_OFF    (2 * H_BYTES)
#define SMEM_MBAR_OFF (2 * H_BYTES + 2 * X_BYTES)
#define SMEM_TOTAL    (SMEM_MBAR_OFF + 16)

__device__ __constant__ float kDampF = (float)(0.1 * 627.5094740631 /
                                               (0.529177210903 * 0.529177210903));

__device__ __forceinline__ uint32_t s2u(const void* p) {
    uint32_t a;
    asm("{ .reg .u64 t; cvta.to.shared.u64 t, %1; cvt.u32.u64 %0, t; }"
        : "=r"(a) : "l"(p));
    return a;
}

__device__ __forceinline__ void mbar_init(uint32_t mbar, uint32_t count) {
    asm volatile("mbarrier.init.shared.b64 [%0], %1;" :: "r"(mbar), "r"(count) : "memory");
}

__device__ __forceinline__ void mbar_expect_tx(uint32_t mbar, uint32_t bytes) {
    asm volatile("mbarrier.arrive.expect_tx.shared.b64 _, [%0], %1;"
                 :: "r"(mbar), "r"(bytes) : "memory");
}

__device__ __forceinline__ void mbar_wait(uint32_t mbar, uint32_t parity) {
    asm volatile(
        "{\n\t"
        ".reg .pred P;\n\t"
        "WAIT_%=:\n\t"
        "mbarrier.try_wait.parity.shared.b64 P, [%0], %1;\n\t"
        "@!P bra WAIT_%=;\n\t"
        "}"
        :: "r"(mbar), "r"(parity) : "memory");
}

// bulk G->S copy with L2 evict-first policy (zero-reuse 302MB stream)
__device__ __forceinline__ void bulk_g2s_ef(uint32_t dst_smem, const void* src_gmem,
                                            uint32_t bytes, uint32_t mbar) {
    asm volatile(
        "{\n\t"
        ".reg .b64 pol;\n\t"
        "createpolicy.fractional.L2::evict_first.b64 pol, 1.0;\n\t"
        "cp.async.bulk.shared::cluster.global.mbarrier::complete_tx::bytes.L2::cache_hint "
        "[%0], [%1], %2, [%3], pol;\n\t"
        "}"
        :: "r"(dst_smem), "l"(src_gmem), "r"(bytes), "r"(mbar) : "memory");
}

extern __shared__ char smem_raw[];

__global__ void __launch_bounds__(D, 3)
force_agg_kernel(const float* __restrict__ ns,
                 const float* __restrict__ hess,
                 float* __restrict__ out, int M) {
    float* Hs = reinterpret_cast<float*>(smem_raw);                 // [2][DD]
    float* xs = reinterpret_cast<float*>(smem_raw + SMEM_X_OFF);    // [2][D]
    const uint32_t mbar0 = s2u(smem_raw + SMEM_MBAR_OFF);
    const uint32_t mbar1 = mbar0 + 8;

    const int t = threadIdx.x;     // 0..95
    const int b = blockIdx.x;

    if (t == 0) {
        mbar_init(mbar0, 1);
        mbar_init(mbar1, 1);
    }
    __syncthreads();

    const int stride = gridDim.x;
    const int cnt = (M - b + stride - 1) / stride;

    const uint32_t Hs_u = s2u(Hs);
    const uint32_t xs_u = s2u(xs);

    // prologue: stage 0 for k=0
    if (t == 0) {
        mbar_expect_tx(mbar0, H_BYTES + X_BYTES);
        bulk_g2s_ef(Hs_u, hess + (size_t)b * DD, H_BYTES, mbar0);
        bulk_g2s_ef(xs_u, ns + (size_t)b * D, X_BYTES, mbar0);
    }

    uint32_t phase0 = 0, phase1 = 0;
    const int c0 = t % D4;         // rotated vec4-column start (conflict-free)

    const size_t mstepH = (size_t)stride * DD;
    const size_t mstepX = (size_t)stride * D;
    const float* hess_next = hess + (size_t)b * DD + mstepH;   // molecule k=1
    const float* ns_next   = ns   + (size_t)b * D  + mstepX;
    float* out_p           = out  + (size_t)b * D  + t;

    for (int k = 0; k < cnt; ++k) {
        const int s = k & 1;

        // prefetch k+1 into stage s^1 (freed by the sync ending iter k-1)
        if (t == 0 && (k + 1) < cnt) {
            const int s2 = s ^ 1;
            const uint32_t mbar_n = s2 ? mbar1 : mbar0;
            mbar_expect_tx(mbar_n, H_BYTES + X_BYTES);
            bulk_g2s_ef(Hs_u + (uint32_t)s2 * H_BYTES, hess_next, H_BYTES, mbar_n);
            bulk_g2s_ef(xs_u + (uint32_t)s2 * X_BYTES, ns_next, X_BYTES, mbar_n);
        }
        hess_next += mstepH;
        ns_next   += mstepX;

        // wait for stage s
        if (s) { mbar_wait(mbar1, phase1); phase1 ^= 1; }
        else   { mbar_wait(mbar0, phase0); phase0 ^= 1; }

        // vectorized dot product: LDS.128 on H row and x, rotated start.
        // 16B-group = (c mod 8): distinct within each 8-lane phase -> bank-free.
        const float4* __restrict__ Hrow4 =
            reinterpret_cast<const float4*>(Hs + (size_t)s * DD + (size_t)t * D);
        const float4* __restrict__ xv4 =
            reinterpret_cast<const float4*>(xs + s * D);

        float a0 = 0.f, a1 = 0.f, a2 = 0.f, a3 = 0.f;
        int c = c0;
        #pragma unroll
        for (int it = 0; it < D4; ++it) {
            float4 h = Hrow4[c];
            float4 xv = xv4[c];
            a0 = fmaf(h.x, xv.x, a0);
            a1 = fmaf(h.y, xv.y, a1);
            a2 = fmaf(h.z, xv.z, a2);
            a3 = fmaf(h.w, xv.w, a3);
            ++c;
            if (c == D4) c = 0;
        }
        const float x_t = (xs + s * D)[t];
        const float acc = fmaf(kDampF, x_t, (a0 + a1) + (a2 + a3));

        *out_p = acc;
        out_p += mstepX;

        // stage s must be fully consumed before iter k+1 refills it;
        // elide on the final iteration (nothing is refilled afterward)
        if ((k + 1) < cnt) __syncthreads();
    }
}

extern "C" void kernel_launch(void* const* d_in, const int* in_sizes, int n_in,
                              void* d_out, int out_size) {
    const float* ns   = (const float*)d_in[0];   // [N_tot,3] -> flat [M*96]
    const float* hess = (const float*)d_in[1];   // [M*96, 96]
    float* out = (float*)d_out;

    const int M = in_sizes[1] / DD;              // 8192

    cudaFuncSetAttribute(force_agg_kernel,
                         cudaFuncAttributeMaxDynamicSharedMemorySize, SMEM_TOTAL);
    force_agg_kernel<<<NBLOCKS, D, SMEM_TOTAL>>>(ns, hess, out, M);
}